// round 3
// baseline (speedup 1.0000x reference)
#include <cuda_runtime.h>
#include <math.h>

#define TT   1024
#define DD   256
#define HH   256
#define LDP  1024

// Scratch (static device globals; no allocation)
__device__ float    g_P[TT*LDP];   // cols [0,256)=k(elu) [256,512)=q(elu) [512,768)=v [768,1024)=skip
__device__ float    g_A[TT*TT];    // masked scores (lower-tri tiles valid)
__device__ float    g_O[TT*HH];    // attention output (numer/denom)
__device__ float    g_H1[TT*HH];
__device__ float    g_H2[TT*HH];
__device__ float    g_H3[TT*HH];
__device__ unsigned g_M[TT*32];    // bit (ti,ki): coeff of kv_{ki+1} in scan result[ti+1]
__device__ float    g_den[TT];
__device__ float    g_ksum[TT], g_qsum[TT];

// Scan simulation scratch: 1025+512+256+128+64+32+16+8+4+2+1 = 2048 elements
__device__ unsigned g_Dm[2048*32];  // down-sweep masks
__device__ unsigned g_Sm[2048*32];  // scanned masks
__device__ int      g_Dg[2048];     // gates: bit0 = start, bit1 = done

// ---------------------------------------------------------------------------
// Exact simulation of jax.lax.associative_scan's recursive bracketing on
// 1024-bit coefficient masks. combine(a,b): mask = (st_b?mask_a:0)|(dn_b?mask_b:0),
// gates = gates_b.  Single block, 1024 threads, levels separated by barriers.
// ---------------------------------------------------------------------------
__global__ void scan_mask_kernel(const int* __restrict__ start, const int* __restrict__ done) {
    const int n[11]   = {1025,512,256,128,64,32,16,8,4,2,1};
    const int off[11] = {0,1025,1537,1793,1921,1985,2017,2033,2041,2045,2047};
    int tid = threadIdx.x;

    // init level 0: element 0 = (s0,z0) mask=0; element i>0 has bit i-1
    for (int idx = tid; idx < 1025*32; idx += blockDim.x) {
        int i = idx >> 5, w = idx & 31;
        unsigned m = 0;
        if (i > 0 && ((i-1) >> 5) == w) m = 1u << ((i-1) & 31);
        g_Dm[idx] = m;
        if (w == 0) g_Dg[i] = (start[i] ? 1 : 0) | (done[i] ? 2 : 0);
    }
    __syncthreads();

    // down-sweep: reduced[i] = combine(e[2i], e[2i+1])
    for (int d = 0; d < 10; d++) {
        int nn = n[d+1];
        int src = off[d], dst = off[d+1];
        for (int idx = tid; idx < nn*32; idx += blockDim.x) {
            int i = idx >> 5, w = idx & 31;
            int gb = g_Dg[src + 2*i + 1];
            unsigned m = 0;
            if (gb & 1) m |= g_Dm[(src + 2*i    )*32 + w];
            if (gb & 2) m |= g_Dm[(src + 2*i + 1)*32 + w];
            g_Dm[(dst + i)*32 + w] = m;
            if (w == 0) g_Dg[dst + i] = gb;
        }
        __syncthreads();
    }

    // top level scanned = itself
    for (int w = tid; w < 32; w += blockDim.x)
        g_Sm[off[10]*32 + w] = g_Dm[off[10]*32 + w];
    __syncthreads();

    // up-sweep: res[0]=e[0]; res[2i+1]=o[i]; res[2i+2]=combine(o[i], e[2i+2])
    for (int d = 9; d >= 0; d--) {
        int nd = n[d];
        int src = off[d], o = off[d+1];
        for (int idx = tid; idx < nd*32; idx += blockDim.x) {
            int pos = idx >> 5, w = idx & 31;
            unsigned m;
            if (pos == 0) {
                m = g_Dm[src*32 + w];
            } else if (pos & 1) {
                m = g_Sm[(o + (pos >> 1))*32 + w];
            } else {
                int i = (pos >> 1) - 1;
                int gb = g_Dg[src + pos];
                m = 0;
                if (gb & 1) m |= g_Sm[(o + i)*32 + w];
                if (gb & 2) m |= g_Dm[(src + pos)*32 + w];
            }
            g_Sm[(src + pos)*32 + w] = m;
        }
        __syncthreads();
    }

    // g_M[t] = scanned element t+1  (reference takes s[1:])
    for (int idx = tid; idx < 1024*32; idx += blockDim.x) {
        int t = idx >> 5, w = idx & 31;
        g_M[idx] = g_Sm[(t + 1)*32 + w];
    }
}

// ---------------------------------------------------------------------------
// Shared GEMM cores: 64x64 block tile, BK=16, 256 threads, 4x4 microtile.
// TT-layout: C[m][n] = sum_k A[m][k]*B[n][k]  (both k-contiguous)
// TN-layout: C[m][n] = sum_k A[m][k]*B[k][n]
// ---------------------------------------------------------------------------
__device__ __forceinline__ void microfma(float acc[4][4], float4 a, float4 b) {
    acc[0][0] += a.x*b.x; acc[0][1] += a.x*b.y; acc[0][2] += a.x*b.z; acc[0][3] += a.x*b.w;
    acc[1][0] += a.y*b.x; acc[1][1] += a.y*b.y; acc[1][2] += a.y*b.z; acc[1][3] += a.y*b.w;
    acc[2][0] += a.z*b.x; acc[2][1] += a.z*b.y; acc[2][2] += a.z*b.z; acc[2][3] += a.z*b.w;
    acc[3][0] += a.w*b.x; acc[3][1] += a.w*b.y; acc[3][2] += a.w*b.z; acc[3][3] += a.w*b.w;
}

__device__ __forceinline__ void gemm_TT_loop(
    const float* __restrict__ A, int lda, int m0,
    const float* __restrict__ B, int ldb, int n0,
    int K, float acc[4][4], float (*As)[64], float (*Bs)[64],
    int tid, int tx, int ty)
{
    int row = tid >> 2, c4 = (tid & 3) << 2;
    for (int k0 = 0; k0 < K; k0 += 16) {
        float4 av = *(const float4*)(A + (size_t)(m0 + row) * lda + k0 + c4);
        float4 bv = *(const float4*)(B + (size_t)(n0 + row) * ldb + k0 + c4);
        __syncthreads();
        As[c4+0][row] = av.x; As[c4+1][row] = av.y; As[c4+2][row] = av.z; As[c4+3][row] = av.w;
        Bs[c4+0][row] = bv.x; Bs[c4+1][row] = bv.y; Bs[c4+2][row] = bv.z; Bs[c4+3][row] = bv.w;
        __syncthreads();
#pragma unroll
        for (int kk = 0; kk < 16; kk++) {
            float4 a = *(const float4*)&As[kk][ty * 4];
            float4 b = *(const float4*)&Bs[kk][tx * 4];
            microfma(acc, a, b);
        }
    }
}

__device__ __forceinline__ void gemm_TN_loop(
    const float* __restrict__ A, int lda, int m0,
    const float* __restrict__ B, int ldb, int n0,
    int K, float acc[4][4], float (*As)[64], float (*Bs)[64],
    int tid, int tx, int ty)
{
    int rowA = tid >> 2, c4A = (tid & 3) << 2;
    int kB = tid >> 4, c4B = (tid & 15) << 2;
    for (int k0 = 0; k0 < K; k0 += 16) {
        float4 av = *(const float4*)(A + (size_t)(m0 + rowA) * lda + k0 + c4A);
        float4 bv = *(const float4*)(B + (size_t)(k0 + kB) * ldb + n0 + c4B);
        __syncthreads();
        As[c4A+0][rowA] = av.x; As[c4A+1][rowA] = av.y; As[c4A+2][rowA] = av.z; As[c4A+3][rowA] = av.w;
        *(float4*)&Bs[kB][c4B] = bv;
        __syncthreads();
#pragma unroll
        for (int kk = 0; kk < 16; kk++) {
            float4 a = *(const float4*)&As[kk][ty * 4];
            float4 b = *(const float4*)&Bs[kk][tx * 4];
            microfma(acc, a, b);
        }
    }
}

// ---------------------------------------------------------------------------
// Projections: k=elu(xWk^T), q=elu(xWq^T), v=xWv^T, skip=xWs^T+bskip
// ---------------------------------------------------------------------------
__global__ void proj_kernel(const float* __restrict__ X,
                            const float* __restrict__ Wk, const float* __restrict__ Wq,
                            const float* __restrict__ Wv, const float* __restrict__ Ws,
                            const float* __restrict__ bskip)
{
    __shared__ float As[16][64], Bs[16][64];
    int tid = threadIdx.x, tx = tid & 15, ty = tid >> 4;
    int bx = blockIdx.x, by = blockIdx.y;
    int wsel = bx >> 2;
    const float* W = (wsel == 0) ? Wk : (wsel == 1) ? Wq : (wsel == 2) ? Wv : Ws;
    int n0 = (bx & 3) * 64;
    int m0 = by * 64;
    float acc[4][4] = {};
    gemm_TT_loop(X, DD, m0, W, DD, n0, DD, acc, As, Bs, tid, tx, ty);
#pragma unroll
    for (int i = 0; i < 4; i++) {
        int t = m0 + ty * 4 + i;
#pragma unroll
        for (int j = 0; j < 4; j++) {
            int c = n0 + tx * 4 + j;
            float v = acc[i][j];
            if (wsel < 2) v = (v > 0.f) ? v : expm1f(v);     // elu
            if (wsel == 3) v += bskip[c];
            g_P[(size_t)t * LDP + wsel * 256 + c] = v;
        }
    }
}

// ---------------------------------------------------------------------------
// Row sums of k and q (for denom = qsum[t] * sum_j mask(t,j)*ksum[j])
// ---------------------------------------------------------------------------
__global__ void rowsum_kernel() {
    int warp = (blockIdx.x * blockDim.x + threadIdx.x) >> 5;   // 0..1023
    int lane = threadIdx.x & 31;
    const float* krow = g_P + (size_t)warp * LDP;
    const float* qrow = krow + 256;
    float ks = 0.f, qs = 0.f;
    for (int c = lane; c < 256; c += 32) { ks += krow[c]; qs += qrow[c]; }
#pragma unroll
    for (int o = 16; o > 0; o >>= 1) {
        ks += __shfl_xor_sync(0xffffffffu, ks, o);
        qs += __shfl_xor_sync(0xffffffffu, qs, o);
    }
    if (lane == 0) { g_ksum[warp] = ks; g_qsum[warp] = qs; }
}

__global__ void denom_kernel() {
    int warp = (blockIdx.x * blockDim.x + threadIdx.x) >> 5;   // row t
    int lane = threadIdx.x & 31;
    unsigned bits = g_M[warp * 32 + lane];
    float s = 0.f;
    while (bits) {
        int b = __ffs(bits) - 1;
        bits &= bits - 1;
        s += g_ksum[lane * 32 + b];
    }
#pragma unroll
    for (int o = 16; o > 0; o >>= 1) s += __shfl_xor_sync(0xffffffffu, s, o);
    if (lane == 0) g_den[warp] = s * g_qsum[warp];
}

// ---------------------------------------------------------------------------
// Masked scores A = (Q K^T) * M. Only lower-triangular tiles computed.
// ---------------------------------------------------------------------------
__global__ void scores_kernel() {
    int bi = blockIdx.x, bt = blockIdx.y;
    if (bi > bt) return;
    __shared__ float As[16][64], Bs[16][64];
    int tid = threadIdx.x, tx = tid & 15, ty = tid >> 4;
    float acc[4][4] = {};
    gemm_TT_loop(g_P + 256, LDP, bt * 64, g_P, LDP, bi * 64, DD, acc, As, Bs, tid, tx, ty);
#pragma unroll
    for (int i = 0; i < 4; i++) {
        int t = bt * 64 + ty * 4 + i;
        const unsigned* Mrow = &g_M[t * 32];
        float4 vs;
        float* vp = (float*)&vs;
#pragma unroll
        for (int j = 0; j < 4; j++) {
            int ki = bi * 64 + tx * 4 + j;
            unsigned bit = (Mrow[ki >> 5] >> (ki & 31)) & 1u;
            vp[j] = bit ? acc[i][j] : 0.f;
        }
        *(float4*)&g_A[(size_t)t * TT + bi * 64 + tx * 4] = vs;
    }
}

// ---------------------------------------------------------------------------
// numer = A @ V (K truncated at diagonal), then divide by clipped denom.
// ---------------------------------------------------------------------------
__global__ void numer_kernel() {
    int bn = blockIdx.x, bt = blockIdx.y;
    __shared__ float As[16][64], Bs[16][64];
    int tid = threadIdx.x, tx = tid & 15, ty = tid >> 4;
    float acc[4][4] = {};
    int K = (bt + 1) * 64;
    gemm_TN_loop(g_A, TT, bt * 64, g_P + 512, LDP, bn * 64, K, acc, As, Bs, tid, tx, ty);
#pragma unroll
    for (int i = 0; i < 4; i++) {
        int t = bt * 64 + ty * 4 + i;
        float inv = 1.f / fmaxf(g_den[t], 1e-5f);
#pragma unroll
        for (int j = 0; j < 4; j++)
            g_O[(size_t)t * HH + bn * 64 + tx * 4 + j] = acc[i][j] * inv;
    }
}

// ---------------------------------------------------------------------------
// MLP GEMMs. MODE 0: h1=mish(O W1^T+b1); 1: h2=mish(h1 W2^T+b2);
//            2: h3=h2 W3^T+b3+skip
// ---------------------------------------------------------------------------
__device__ __forceinline__ float mishf(float v) {
    float sp = (v > 20.f) ? v : log1pf(expf(v));
    return v * tanhf(sp);
}

template <int MODE>
__global__ void mlp_kernel(const float* __restrict__ W, const float* __restrict__ bias) {
    int bn = blockIdx.x, bm = blockIdx.y;
    __shared__ float As[16][64], Bs[16][64];
    int tid = threadIdx.x, tx = tid & 15, ty = tid >> 4;
    const float* Ain = (MODE == 0) ? g_O : (MODE == 1) ? g_H1 : g_H2;
    float* Cout = (MODE == 0) ? g_H1 : (MODE == 1) ? g_H2 : g_H3;
    float acc[4][4] = {};
    gemm_TT_loop(Ain, HH, bm * 64, W, HH, bn * 64, HH, acc, As, Bs, tid, tx, ty);
#pragma unroll
    for (int i = 0; i < 4; i++) {
        int t = bm * 64 + ty * 4 + i;
#pragma unroll
        for (int j = 0; j < 4; j++) {
            int c = bn * 64 + tx * 4 + j;
            float v = acc[i][j] + bias[c];
            if (MODE < 2) v = mishf(v);
            else          v += g_P[(size_t)t * LDP + 768 + c];
            Cout[(size_t)t * HH + c] = v;
        }
    }
}

// ---------------------------------------------------------------------------
// Per-row LayerNorm (256 threads = 1 row)
// ---------------------------------------------------------------------------
__global__ void ln_kernel(const float* __restrict__ w, const float* __restrict__ b,
                          float* __restrict__ out) {
    int row = blockIdx.x, tid = threadIdx.x;
    float v = g_H3[(size_t)row * HH + tid];
    __shared__ float sh[8];
    float s = v;
#pragma unroll
    for (int o = 16; o > 0; o >>= 1) s += __shfl_xor_sync(0xffffffffu, s, o);
    if ((tid & 31) == 0) sh[tid >> 5] = s;
    __syncthreads();
    float tot = 0.f;
#pragma unroll
    for (int i = 0; i < 8; i++) tot += sh[i];
    float mean = tot * (1.f / 256.f);
    float d = v - mean;
    float s2 = d * d;
#pragma unroll
    for (int o = 16; o > 0; o >>= 1) s2 += __shfl_xor_sync(0xffffffffu, s2, o);
    __syncthreads();
    if ((tid & 31) == 0) sh[tid >> 5] = s2;
    __syncthreads();
    float tot2 = 0.f;
#pragma unroll
    for (int i = 0; i < 8; i++) tot2 += sh[i];
    float var = tot2 * (1.f / 256.f);
    out[(size_t)row * HH + tid] = d * rsqrtf(var + 1e-5f) * w[tid] + b[tid];
}

// ---------------------------------------------------------------------------
extern "C" void kernel_launch(void* const* d_in, const int* in_sizes, int n_in,
                              void* d_out, int out_size) {
    const float* x     = (const float*)d_in[0];
    const int*   start = (const int*)d_in[3];
    const int*   done  = (const int*)d_in[4];
    const float* Wk = (const float*)d_in[5];
    const float* Wq = (const float*)d_in[6];
    const float* Wv = (const float*)d_in[7];
    const float* Ws = (const float*)d_in[8];
    const float* bskip = (const float*)d_in[9];
    const float* W1 = (const float*)d_in[10];
    const float* b1 = (const float*)d_in[11];
    const float* W2 = (const float*)d_in[12];
    const float* b2 = (const float*)d_in[13];
    const float* W3 = (const float*)d_in[14];
    const float* b3 = (const float*)d_in[15];
    const float* lnw = (const float*)d_in[16];
    const float* lnb = (const float*)d_in[17];
    float* out = (float*)d_out;

    scan_mask_kernel<<<1, 1024>>>(start, done);
    proj_kernel<<<dim3(16, 16), 256>>>(x, Wk, Wq, Wv, Ws, bskip);
    rowsum_kernel<<<128, 256>>>();
    denom_kernel<<<128, 256>>>();
    scores_kernel<<<dim3(16, 16), 256>>>();
    numer_kernel<<<dim3(4, 16), 256>>>();
    mlp_kernel<0><<<dim3(4, 16), 256>>>(W1, b1);
    mlp_kernel<1><<<dim3(4, 16), 256>>>(W2, b2);
    mlp_kernel<2><<<dim3(4, 16), 256>>>(W3, b3);
    ln_kernel<<<1024, 256>>>(lnw, lnb, out);
}